// round 3
// baseline (speedup 1.0000x reference)
#include <cuda_runtime.h>
#include <cstdint>

#define NN 20000
#define EE 320000

// ---------------- static scratch (no allocations allowed) ----------------
__device__ __align__(16) float g_A[NN * 1536];   // agg-side GEMM output
__device__ __align__(16) float g_B[NN * 1536];   // self-side GEMM output
__device__ __align__(16) float g_H[NN * 1536];   // hidden activations
__device__ int   g_deg[NN];
__device__ int   g_fill[NN];
__device__ int   g_rowptr[NN + 1];
__device__ int   g_col[EE];
__device__ float g_dinv[NN];

// compile-time buffer selector: 0 = external arg, 1 = g_A, 2 = g_B, 3 = g_H
template <int S>
__device__ __forceinline__ float* buf(float* ext) {
    if constexpr (S == 1) return g_A;
    else if constexpr (S == 2) return g_B;
    else if constexpr (S == 3) return g_H;
    else return ext;
}
template <int S>
__device__ __forceinline__ const float* cbuf(const float* ext) {
    if constexpr (S == 1) return g_A;
    else if constexpr (S == 2) return g_B;
    else if constexpr (S == 3) return g_H;
    else return ext;
}

// ---------------- CSR construction (edge_index is int32: JAX x64 disabled) --
__global__ void zero_counts_kernel() {
    int i = blockIdx.x * blockDim.x + threadIdx.x;
    if (i < NN) { g_deg[i] = 0; g_fill[i] = 0; }
}

__global__ void count_deg_kernel(const int* __restrict__ ei) {
    int e = blockIdx.x * blockDim.x + threadIdx.x;
    if (e < EE) {
        int dst = ei[EE + e];
        if ((unsigned)dst < NN) atomicAdd(&g_deg[dst], 1);
    }
}

// single-block scan -> exclusive rowptr, plus deg_inv
__global__ void scan_deg_kernel() {
    __shared__ int sh[1024];
    int tid = threadIdx.x;
    int carry = 0;
    if (tid == 0) g_rowptr[0] = 0;
    for (int base = 0; base < NN; base += 1024) {
        int i = base + tid;
        int v = (i < NN) ? g_deg[i] : 0;
        sh[tid] = v;
        __syncthreads();
        for (int off = 1; off < 1024; off <<= 1) {
            int t = (tid >= off) ? sh[tid - off] : 0;
            __syncthreads();
            sh[tid] += t;
            __syncthreads();
        }
        if (i < NN) {
            g_rowptr[i + 1] = carry + sh[tid];
            g_dinv[i] = 1.0f / fmaxf((float)v, 1.0f);
        }
        int last = sh[1023];
        __syncthreads();
        carry += last;
    }
}

__global__ void fill_csr_kernel(const int* __restrict__ ei) {
    int e = blockIdx.x * blockDim.x + threadIdx.x;
    if (e < EE) {
        int src = ei[e];
        int dst = ei[EE + e];
        if ((unsigned)dst < NN && (unsigned)src < NN) {
            int p = atomicAdd(&g_fill[dst], 1);
            g_col[g_rowptr[dst] + p] = src;
        }
    }
}

// ---------------- fp32 SGEMM: C[M,Nd] = A[M,Kd] @ W[Kd,Nd] ----------------
// BM=128 BN=128 BK=8, 256 threads, 8x8 per thread. Requires Nd%128==0, Kd%8==0.
template <int AS, int CS>
__global__ __launch_bounds__(256) void sgemm_kernel(
    const float* __restrict__ Aext, const float* __restrict__ W,
    float* __restrict__ Cext, int M, int Kd, int Nd)
{
    const float* A = cbuf<AS>(Aext);
    float* C = buf<CS>(Cext);

    __shared__ float As[8][128];
    __shared__ float Bs[8][128];

    const int tid = threadIdx.x;
    const int bx = blockIdx.x;
    const int by = blockIdx.y;

    const int arow = tid >> 1;
    const int acol = (tid & 1) * 4;
    const int brow = tid >> 5;
    const int bcol = (tid & 31) * 4;

    const int tx = tid & 15;
    const int ty = tid >> 4;

    float acc[8][8];
#pragma unroll
    for (int i = 0; i < 8; i++)
#pragma unroll
        for (int j = 0; j < 8; j++) acc[i][j] = 0.f;

    const float* Aptr = A + (size_t)(by * 128) * Kd;
    const float* Wptr = W + bx * 128;
    const int grow_a = by * 128 + arow;

    for (int k0 = 0; k0 < Kd; k0 += 8) {
        float4 av = make_float4(0.f, 0.f, 0.f, 0.f);
        if (grow_a < M)
            av = *(const float4*)(Aptr + (size_t)arow * Kd + k0 + acol);
        As[acol + 0][arow] = av.x;
        As[acol + 1][arow] = av.y;
        As[acol + 2][arow] = av.z;
        As[acol + 3][arow] = av.w;

        float4 wv = *(const float4*)(Wptr + (size_t)(k0 + brow) * Nd + bcol);
        *(float4*)&Bs[brow][bcol] = wv;

        __syncthreads();

#pragma unroll
        for (int kk = 0; kk < 8; kk++) {
            float ar[8], br[8];
            ((float4*)ar)[0] = *(float4*)&As[kk][ty * 8];
            ((float4*)ar)[1] = *(float4*)&As[kk][ty * 8 + 4];
            ((float4*)br)[0] = *(float4*)&Bs[kk][tx * 8];
            ((float4*)br)[1] = *(float4*)&Bs[kk][tx * 8 + 4];
#pragma unroll
            for (int i = 0; i < 8; i++)
#pragma unroll
                for (int j = 0; j < 8; j++)
                    acc[i][j] += ar[i] * br[j];
        }
        __syncthreads();
    }

    const int crow0 = by * 128 + ty * 8;
    const int ccol0 = bx * 128 + tx * 8;
#pragma unroll
    for (int i = 0; i < 8; i++) {
        int r = crow0 + i;
        if (r < M) {
            *(float4*)(C + (size_t)r * Nd + ccol0)     = *(float4*)&acc[i][0];
            *(float4*)(C + (size_t)r * Nd + ccol0 + 4) = *(float4*)&acc[i][4];
        }
    }
}

// small-N GEMM for the final 256->5 linear (A external = d_out h region)
template <int CS>
__global__ void gemm_small_kernel(const float* __restrict__ Aext,
                                  const float* __restrict__ W,
                                  int M, int Kd, int Nd)
{
    float* C = buf<CS>(nullptr);
    int idx = blockIdx.x * blockDim.x + threadIdx.x;
    if (idx >= M * Nd) return;
    int row = idx / Nd, c = idx % Nd;
    const float* a = Aext + (size_t)row * Kd;
    float acc = 0.f;
    for (int k = 0; k < Kd; k++) acc += a[k] * W[k * Nd + c];
    C[idx] = acc;
}

// ---------------- combine: out = relu(deg_inv * agg(g_A) + g_B + bias) ----
// F = VPT * 128; one block per node.
template <int VPT, int OS>
__global__ __launch_bounds__(128) void combine_kernel(
    const float* __restrict__ bias, float* __restrict__ outExt, int do_relu)
{
    float* out = buf<OS>(outExt);
    const int node = blockIdx.x;
    const int tid = threadIdx.x;
    const int F = VPT * 128;
    const int s = g_rowptr[node];
    const int e = g_rowptr[node + 1];

    float acc[VPT];
#pragma unroll
    for (int v = 0; v < VPT; v++) acc[v] = 0.f;

    __shared__ int nb[128];
    for (int base = s; base < e; base += 128) {
        int cnt = min(128, e - base);
        if (tid < cnt) nb[tid] = g_col[base + tid];
        __syncthreads();
        for (int j = 0; j < cnt; j++) {
            const float* row = g_A + (size_t)nb[j] * F;
#pragma unroll
            for (int v = 0; v < VPT; v++) acc[v] += row[tid + v * 128];
        }
        __syncthreads();
    }

    const float di = g_dinv[node];
#pragma unroll
    for (int v = 0; v < VPT; v++) {
        int c = tid + v * 128;
        float r = acc[v] * di + g_B[(size_t)node * F + c] + bias[c];
        if (do_relu) r = fmaxf(r, 0.f);
        out[(size_t)node * F + c] = r;
    }
}

// final layer combine (F=5, no relu): one warp per node, Ag=g_A, Bself=g_B
__global__ void combine5_kernel(const float* __restrict__ bias,
                                float* __restrict__ out)
{
    int node = blockIdx.x * 4 + (threadIdx.x >> 5);
    if (node >= NN) return;
    int lane = threadIdx.x & 31;
    if (lane >= 5) return;
    int s = g_rowptr[node], e = g_rowptr[node + 1];
    float acc = 0.f;
    for (int j = s; j < e; j++) {
        int src = g_col[j];
        acc += g_A[src * 5 + lane];
    }
    float r = acc * g_dinv[node] + g_B[node * 5 + lane] + bias[lane];
    out[node * 5 + lane] = r;
}

// ---------------- launch ----------------
extern "C" void kernel_launch(void* const* d_in, const int* in_sizes, int n_in,
                              void* d_out, int out_size)
{
    const float* x  = (const float*)d_in[0];
    const int*   ei = (const int*)d_in[1];   // int32: JAX x64 disabled
    const float* Wl1 = (const float*)d_in[2];
    const float* Wr1 = (const float*)d_in[3];
    const float* b1  = (const float*)d_in[4];
    const float* Wl2 = (const float*)d_in[5];
    const float* Wr2 = (const float*)d_in[6];
    const float* b2  = (const float*)d_in[7];
    const float* Wl3 = (const float*)d_in[8];
    const float* Wr3 = (const float*)d_in[9];
    const float* b3  = (const float*)d_in[10];
    const float* Wl4 = (const float*)d_in[11];
    const float* Wr4 = (const float*)d_in[12];
    const float* b4  = (const float*)d_in[13];
    const float* Wl5 = (const float*)d_in[14];
    const float* Wr5 = (const float*)d_in[15];
    const float* b5  = (const float*)d_in[16];

    float* out = (float*)d_out;
    float* out_h   = out;                      // [NN, 256]
    float* out_cls = out + (size_t)NN * 256;   // [NN, 5]

    // ---- CSR build ----
    zero_counts_kernel<<<(NN + 255) / 256, 256>>>();
    count_deg_kernel<<<(EE + 255) / 256, 256>>>(ei);
    scan_deg_kernel<<<1, 1024>>>();
    fill_csr_kernel<<<(EE + 255) / 256, 256>>>(ei);

    const int M = NN;
    dim3 blk(256);
    const int gy = (M + 127) / 128;

    // ---- Layer 1: 768 -> 1536 (input x external) ----
    sgemm_kernel<0, 1><<<dim3(12, gy), blk>>>(x, Wl1, nullptr, M, 768, 1536);
    sgemm_kernel<0, 2><<<dim3(12, gy), blk>>>(x, Wr1, nullptr, M, 768, 1536);
    combine_kernel<12, 3><<<NN, 128>>>(b1, nullptr, 1);   // -> g_H

    // ---- Layer 2: 1536 -> 768 ----
    sgemm_kernel<3, 1><<<dim3(6, gy), blk>>>(nullptr, Wl2, nullptr, M, 1536, 768);
    sgemm_kernel<3, 2><<<dim3(6, gy), blk>>>(nullptr, Wr2, nullptr, M, 1536, 768);
    combine_kernel<6, 3><<<NN, 128>>>(b2, nullptr, 1);    // -> g_H (in-place swap ok)

    // ---- Layer 3: 768 -> 384 ----
    sgemm_kernel<3, 1><<<dim3(3, gy), blk>>>(nullptr, Wl3, nullptr, M, 768, 384);
    sgemm_kernel<3, 2><<<dim3(3, gy), blk>>>(nullptr, Wr3, nullptr, M, 768, 384);
    combine_kernel<3, 3><<<NN, 128>>>(b3, nullptr, 1);    // -> g_H

    // ---- Layer 4: 384 -> 256 (h output) ----
    sgemm_kernel<3, 1><<<dim3(2, gy), blk>>>(nullptr, Wl4, nullptr, M, 384, 256);
    sgemm_kernel<3, 2><<<dim3(2, gy), blk>>>(nullptr, Wr4, nullptr, M, 384, 256);
    combine_kernel<2, 0><<<NN, 128>>>(b4, out_h, 1);      // -> d_out h region

    // ---- Layer 5: 256 -> 5 (no relu) ----
    gemm_small_kernel<1><<<(NN * 5 + 255) / 256, 256>>>(out_h, Wl5, M, 256, 5);
    gemm_small_kernel<2><<<(NN * 5 + 255) / 256, 256>>>(out_h, Wr5, M, 256, 5);
    combine5_kernel<<<(NN + 3) / 4, 128>>>(b5, out_cls);
}

// round 5
// speedup vs baseline: 1.6123x; 1.6123x over previous
#include <cuda_runtime.h>
#include <cuda_bf16.h>
#include <cstdint>

#define NN 20000
#define EE 320000

// ================= static scratch =================
__device__ __align__(16) float g_A[NN * 1536];
__device__ __align__(16) float g_B[NN * 1536];
__device__ __align__(16) float g_H[NN * 1536];
// bf16 transposed-split weights: [Wl layers 1-4 | Wr layers 1-4]
#define WSEG 2752512
__device__ __align__(16) __nv_bfloat16 g_Wh[2 * WSEG];
__device__ __align__(16) __nv_bfloat16 g_Wlo[2 * WSEG];
__device__ int   g_deg[NN];
__device__ int   g_fill[NN];
__device__ int   g_rowptr[NN + 1];
__device__ int   g_col[EE];
__device__ float g_dinv[NN];

template <int S>
__device__ __forceinline__ float* buf(float* ext) {
    if constexpr (S == 1) return g_A;
    else if constexpr (S == 2) return g_B;
    else if constexpr (S == 3) return g_H;
    else return ext;
}
template <int S>
__device__ __forceinline__ const float* cbuf(const float* ext) {
    if constexpr (S == 1) return g_A;
    else if constexpr (S == 2) return g_B;
    else if constexpr (S == 3) return g_H;
    else return ext;
}

// ================= mma/ldmatrix helpers (baseline PTX, sm_80+) =================
__device__ __forceinline__ uint32_t smem_u32(const void* p) {
    uint32_t a;
    asm("{ .reg .u64 t; cvta.to.shared.u64 t, %1; cvt.u32.u64 %0, t; }" : "=r"(a) : "l"(p));
    return a;
}
__device__ __forceinline__ void ldm_x4(uint32_t* r, uint32_t addr) {
    asm volatile("ldmatrix.sync.aligned.m8n8.x4.shared.b16 {%0,%1,%2,%3}, [%4];"
        : "=r"(r[0]), "=r"(r[1]), "=r"(r[2]), "=r"(r[3]) : "r"(addr));
}
__device__ __forceinline__ void mma16816(float* c, const uint32_t* a, const uint32_t* b) {
    asm volatile("mma.sync.aligned.m16n8k16.row.col.f32.bf16.bf16.f32 "
        "{%0,%1,%2,%3}, {%4,%5,%6,%7}, {%8,%9}, {%0,%1,%2,%3};"
        : "+f"(c[0]), "+f"(c[1]), "+f"(c[2]), "+f"(c[3])
        : "r"(a[0]), "r"(a[1]), "r"(a[2]), "r"(a[3]), "r"(b[0]), "r"(b[1]));
}
__device__ __forceinline__ uint32_t sw128(uint32_t off) {
    return off ^ ((off >> 3) & 0x70);
}

// ================= CSR construction (edge_index int32) =================
__global__ void zero_counts_kernel() {
    int i = blockIdx.x * blockDim.x + threadIdx.x;
    if (i < NN) { g_deg[i] = 0; g_fill[i] = 0; }
}
__global__ void count_deg_kernel(const int* __restrict__ ei) {
    int e = blockIdx.x * blockDim.x + threadIdx.x;
    if (e < EE) {
        int dst = ei[EE + e];
        if ((unsigned)dst < NN) atomicAdd(&g_deg[dst], 1);
    }
}
__global__ void scan_deg_kernel() {
    __shared__ int sh[1024];
    int tid = threadIdx.x;
    int carry = 0;
    if (tid == 0) g_rowptr[0] = 0;
    for (int base = 0; base < NN; base += 1024) {
        int i = base + tid;
        int v = (i < NN) ? g_deg[i] : 0;
        sh[tid] = v;
        __syncthreads();
        for (int off = 1; off < 1024; off <<= 1) {
            int t = (tid >= off) ? sh[tid - off] : 0;
            __syncthreads();
            sh[tid] += t;
            __syncthreads();
        }
        if (i < NN) {
            g_rowptr[i + 1] = carry + sh[tid];
            g_dinv[i] = 1.0f / fmaxf((float)v, 1.0f);
        }
        int last = sh[1023];
        __syncthreads();
        carry += last;
    }
}
__global__ void fill_csr_kernel(const int* __restrict__ ei) {
    int e = blockIdx.x * blockDim.x + threadIdx.x;
    if (e < EE) {
        int src = ei[e];
        int dst = ei[EE + e];
        if ((unsigned)dst < NN && (unsigned)src < NN) {
            int p = atomicAdd(&g_fill[dst], 1);
            g_col[g_rowptr[dst] + p] = src;
        }
    }
}

// ================= weight prep: transpose + bf16 hi/lo split =================
// out[n*K + k] from W[k*N + n]
__global__ void wprep_kernel(const float* __restrict__ W, int K, int N, int off) {
    int idx = blockIdx.x * blockDim.x + threadIdx.x;
    if (idx >= K * N) return;
    int n = idx / K, k = idx - n * K;
    float w = W[(size_t)k * N + n];
    __nv_bfloat16 hi = __float2bfloat16(w);
    float lo = w - __bfloat162float(hi);
    g_Wh[off + idx] = hi;
    g_Wlo[off + idx] = __float2bfloat16(lo);
}

// ================= HMMA GEMM: C[M,Nd] = A[M,Kd] @ W[Kd,Nd] =================
// W pre-transposed+split as [Nd][Kd] bf16 at g_Wh/g_Wlo + woff.
// 3-term bf16 split: D = Ah*Wh + Ah*Wl + Al*Wh.
// BM=BN=128, BK=32, 256 threads, 8 warps (2 m x 4 n), warp tile 64x32.
// smem rows are 128B: halves 0..31 = hi, 32..63 = lo, SW128 swizzle.
template <int AS, int CS>
__global__ __launch_bounds__(256) void bgemm_kernel(
    const float* __restrict__ Aext, int woff,
    float* __restrict__ Cext, int M, int Kd, int Nd)
{
    __shared__ __align__(128) uint8_t sA[128 * 128];
    __shared__ __align__(128) uint8_t sB[128 * 128];

    const float* A = cbuf<AS>(Aext);
    float* C = buf<CS>(Cext);
    const __nv_bfloat16* Wh = g_Wh + woff;
    const __nv_bfloat16* Wl = g_Wlo + woff;

    const int tid = threadIdx.x;
    const int wid = tid >> 5;
    const int lane = tid & 31;
    const int m0 = blockIdx.y * 128;
    const int n0 = blockIdx.x * 128;
    const int warp_m = (wid & 1) * 64;
    const int warp_n = (wid >> 1) * 32;

    const uint32_t sAb = smem_u32(sA);
    const uint32_t sBb = smem_u32(sB);

    // load-thread mapping: row = tid>>1 (0..127), cb = (tid&1)*16 (k-halves)
    const int lrow = tid >> 1;
    const int lcb  = (tid & 1) * 16;
    const bool arow_ok = (m0 + lrow) < M;
    const float* Arow = A + (size_t)(m0 + lrow) * Kd;
    const __nv_bfloat16* Whrow = Wh + (size_t)(n0 + lrow) * Kd;
    const __nv_bfloat16* Wlrow = Wl + (size_t)(n0 + lrow) * Kd;

    float acc[4][4][4];
#pragma unroll
    for (int mi = 0; mi < 4; mi++)
#pragma unroll
        for (int ni = 0; ni < 4; ni++)
#pragma unroll
            for (int q = 0; q < 4; q++) acc[mi][ni][q] = 0.f;

    // ldmatrix lane addressing
    const int sub = lane >> 3;
    const int lr  = lane & 7;

    for (int k0 = 0; k0 < Kd; k0 += 32) {
        // ---- issue global loads (overlaps with prior MMA phase) ----
        float4 av[4];
#pragma unroll
        for (int j = 0; j < 4; j++) {
            av[j] = make_float4(0.f, 0.f, 0.f, 0.f);
            if (arow_ok) av[j] = *(const float4*)(Arow + k0 + lcb + j * 4);
        }
        uint4 bh0 = *(const uint4*)(Whrow + k0 + lcb);
        uint4 bh1 = *(const uint4*)(Whrow + k0 + lcb + 8);
        uint4 bl0 = *(const uint4*)(Wlrow + k0 + lcb);
        uint4 bl1 = *(const uint4*)(Wlrow + k0 + lcb + 8);

        __syncthreads();   // prior MMA phase done; safe to overwrite smem

        // ---- A: fp32 -> hi/lo bf16, swizzled store ----
        {
            uint32_t hp[8], lp[8];
#pragma unroll
            for (int j = 0; j < 4; j++) {
                float vx[4] = {av[j].x, av[j].y, av[j].z, av[j].w};
#pragma unroll
                for (int q = 0; q < 2; q++) {
                    __nv_bfloat16 h0 = __float2bfloat16(vx[q * 2]);
                    __nv_bfloat16 h1 = __float2bfloat16(vx[q * 2 + 1]);
                    __nv_bfloat16 l0 = __float2bfloat16(vx[q * 2] - __bfloat162float(h0));
                    __nv_bfloat16 l1 = __float2bfloat16(vx[q * 2 + 1] - __bfloat162float(h1));
                    __nv_bfloat162 hv = __halves2bfloat162(h0, h1);
                    __nv_bfloat162 lv = __halves2bfloat162(l0, l1);
                    hp[j * 2 + q] = *(uint32_t*)&hv;
                    lp[j * 2 + q] = *(uint32_t*)&lv;
                }
            }
            uint32_t base = lrow * 128 + lcb * 2;
            *(uint4*)(sA + sw128(base))           = make_uint4(hp[0], hp[1], hp[2], hp[3]);
            *(uint4*)(sA + sw128(base + 16))      = make_uint4(hp[4], hp[5], hp[6], hp[7]);
            *(uint4*)(sA + sw128(base + 64))      = make_uint4(lp[0], lp[1], lp[2], lp[3]);
            *(uint4*)(sA + sw128(base + 64 + 16)) = make_uint4(lp[4], lp[5], lp[6], lp[7]);
        }
        // ---- B: pre-split bf16, swizzled store ----
        {
            uint32_t base = lrow * 128 + lcb * 2;
            *(uint4*)(sB + sw128(base))           = bh0;
            *(uint4*)(sB + sw128(base + 16))      = bh1;
            *(uint4*)(sB + sw128(base + 64))      = bl0;
            *(uint4*)(sB + sw128(base + 64 + 16)) = bl1;
        }
        __syncthreads();

        // ---- MMA phase: 2 k16 steps ----
#pragma unroll
        for (int ks = 0; ks < 2; ks++) {
            uint32_t ah[4][4], al[4][4];
#pragma unroll
            for (int mi = 0; mi < 4; mi++) {
                int row = warp_m + mi * 16 + (sub & 1) * 8 + lr;
                uint32_t kb = ks * 32 + (sub >> 1) * 16;
                ldm_x4(ah[mi], sAb + sw128(row * 128 + kb));
                ldm_x4(al[mi], sAb + sw128(row * 128 + kb + 64));
            }
            uint32_t bh[2][4], bl[2][4];
#pragma unroll
            for (int np = 0; np < 2; np++) {
                int row = warp_n + np * 16 + (sub >> 1) * 8 + lr;
                uint32_t kb = ks * 32 + (sub & 1) * 16;
                ldm_x4(bh[np], sBb + sw128(row * 128 + kb));
                ldm_x4(bl[np], sBb + sw128(row * 128 + kb + 64));
            }
#pragma unroll
            for (int mi = 0; mi < 4; mi++)
#pragma unroll
                for (int ni = 0; ni < 4; ni++) {
                    const uint32_t* ph = &bh[ni >> 1][(ni & 1) * 2];
                    const uint32_t* pl = &bl[ni >> 1][(ni & 1) * 2];
                    mma16816(acc[mi][ni], ah[mi], ph);
                    mma16816(acc[mi][ni], ah[mi], pl);
                    mma16816(acc[mi][ni], al[mi], ph);
                }
        }
    }

    // ---- epilogue ----
    const int g = lane >> 2;
    const int t = lane & 3;
#pragma unroll
    for (int mi = 0; mi < 4; mi++) {
        int r0 = m0 + warp_m + mi * 16 + g;
        int r1 = r0 + 8;
#pragma unroll
        for (int ni = 0; ni < 4; ni++) {
            int col = n0 + warp_n + ni * 8 + t * 2;
            if (r0 < M) *(float2*)(C + (size_t)r0 * Nd + col) = make_float2(acc[mi][ni][0], acc[mi][ni][1]);
            if (r1 < M) *(float2*)(C + (size_t)r1 * Nd + col) = make_float2(acc[mi][ni][2], acc[mi][ni][3]);
        }
    }
}

// ================= small-N GEMM for the final 256->5 linear =================
template <int CS>
__global__ void gemm_small_kernel(const float* __restrict__ Aext,
                                  const float* __restrict__ W,
                                  int M, int Kd, int Nd)
{
    float* C = buf<CS>(nullptr);
    int idx = blockIdx.x * blockDim.x + threadIdx.x;
    if (idx >= M * Nd) return;
    int row = idx / Nd, c = idx % Nd;
    const float* a = Aext + (size_t)row * Kd;
    float acc = 0.f;
    for (int k = 0; k < Kd; k++) acc += a[k] * W[k * Nd + c];
    C[idx] = acc;
}

// ================= combine: out = relu(deg_inv * agg(g_A) + g_B + bias) ====
template <int VPT, int OS>
__global__ __launch_bounds__(128) void combine_kernel(
    const float* __restrict__ bias, float* __restrict__ outExt, int do_relu)
{
    float* out = buf<OS>(outExt);
    const int node = blockIdx.x;
    const int tid = threadIdx.x;
    const int F = VPT * 128;
    const int s = g_rowptr[node];
    const int e = g_rowptr[node + 1];

    float acc[VPT];
#pragma unroll
    for (int v = 0; v < VPT; v++) acc[v] = 0.f;

    __shared__ int nb[128];
    for (int base = s; base < e; base += 128) {
        int cnt = min(128, e - base);
        if (tid < cnt) nb[tid] = g_col[base + tid];
        __syncthreads();
        for (int j = 0; j < cnt; j++) {
            const float* row = g_A + (size_t)nb[j] * F;
#pragma unroll
            for (int v = 0; v < VPT; v++) acc[v] += row[tid + v * 128];
        }
        __syncthreads();
    }

    const float di = g_dinv[node];
#pragma unroll
    for (int v = 0; v < VPT; v++) {
        int c = tid + v * 128;
        float r = acc[v] * di + g_B[(size_t)node * F + c] + bias[c];
        if (do_relu) r = fmaxf(r, 0.f);
        out[(size_t)node * F + c] = r;
    }
}

__global__ void combine5_kernel(const float* __restrict__ bias,
                                float* __restrict__ out)
{
    int node = blockIdx.x * 4 + (threadIdx.x >> 5);
    if (node >= NN) return;
    int lane = threadIdx.x & 31;
    if (lane >= 5) return;
    int s = g_rowptr[node], e = g_rowptr[node + 1];
    float acc = 0.f;
    for (int j = s; j < e; j++) acc += g_A[g_col[j] * 5 + lane];
    out[node * 5 + lane] = acc * g_dinv[node] + g_B[node * 5 + lane] + bias[lane];
}

// ================= launch =================
extern "C" void kernel_launch(void* const* d_in, const int* in_sizes, int n_in,
                              void* d_out, int out_size)
{
    const float* x  = (const float*)d_in[0];
    const int*   ei = (const int*)d_in[1];
    const float* Wl1 = (const float*)d_in[2];
    const float* Wr1 = (const float*)d_in[3];
    const float* b1  = (const float*)d_in[4];
    const float* Wl2 = (const float*)d_in[5];
    const float* Wr2 = (const float*)d_in[6];
    const float* b2  = (const float*)d_in[7];
    const float* Wl3 = (const float*)d_in[8];
    const float* Wr3 = (const float*)d_in[9];
    const float* b3  = (const float*)d_in[10];
    const float* Wl4 = (const float*)d_in[11];
    const float* Wr4 = (const float*)d_in[12];
    const float* b4  = (const float*)d_in[13];
    const float* Wl5 = (const float*)d_in[14];
    const float* Wr5 = (const float*)d_in[15];
    const float* b5  = (const float*)d_in[16];

    float* out = (float*)d_out;
    float* out_h   = out;                      // [NN, 256]
    float* out_cls = out + (size_t)NN * 256;   // [NN, 5]

    // ---- CSR build ----
    zero_counts_kernel<<<(NN + 255) / 256, 256>>>();
    count_deg_kernel<<<(EE + 255) / 256, 256>>>(ei);
    scan_deg_kernel<<<1, 1024>>>();
    fill_csr_kernel<<<(EE + 255) / 256, 256>>>(ei);

    // ---- weight prep: transpose + hi/lo split (layers 1-4) ----
    const int OFF1 = 0, OFF2 = 1179648, OFF3 = 2359296, OFF4 = 2654208;
    wprep_kernel<<<(768 * 1536 + 255) / 256, 256>>>(Wl1, 768, 1536, OFF1);
    wprep_kernel<<<(1536 * 768 + 255) / 256, 256>>>(Wl2, 1536, 768, OFF2);
    wprep_kernel<<<(768 * 384 + 255) / 256, 256>>>(Wl3, 768, 384, OFF3);
    wprep_kernel<<<(384 * 256 + 255) / 256, 256>>>(Wl4, 384, 256, OFF4);
    wprep_kernel<<<(768 * 1536 + 255) / 256, 256>>>(Wr1, 768, 1536, WSEG + OFF1);
    wprep_kernel<<<(1536 * 768 + 255) / 256, 256>>>(Wr2, 1536, 768, WSEG + OFF2);
    wprep_kernel<<<(768 * 384 + 255) / 256, 256>>>(Wr3, 768, 384, WSEG + OFF3);
    wprep_kernel<<<(384 * 256 + 255) / 256, 256>>>(Wr4, 384, 256, WSEG + OFF4);

    const int M = NN;
    const int gy = (M + 127) / 128;   // 157

    // ---- Layer 1: 768 -> 1536 ----
    bgemm_kernel<0, 1><<<dim3(12, gy), 256>>>(x, OFF1, nullptr, M, 768, 1536);
    bgemm_kernel<0, 2><<<dim3(12, gy), 256>>>(x, WSEG + OFF1, nullptr, M, 768, 1536);
    combine_kernel<12, 3><<<NN, 128>>>(b1, nullptr, 1);   // -> g_H

    // ---- Layer 2: 1536 -> 768 ----
    bgemm_kernel<3, 1><<<dim3(6, gy), 256>>>(nullptr, OFF2, nullptr, M, 1536, 768);
    bgemm_kernel<3, 2><<<dim3(6, gy), 256>>>(nullptr, WSEG + OFF2, nullptr, M, 1536, 768);
    combine_kernel<6, 3><<<NN, 128>>>(b2, nullptr, 1);    // -> g_H

    // ---- Layer 3: 768 -> 384 ----
    bgemm_kernel<3, 1><<<dim3(3, gy), 256>>>(nullptr, OFF3, nullptr, M, 768, 384);
    bgemm_kernel<3, 2><<<dim3(3, gy), 256>>>(nullptr, WSEG + OFF3, nullptr, M, 768, 384);
    combine_kernel<3, 3><<<NN, 128>>>(b3, nullptr, 1);    // -> g_H

    // ---- Layer 4: 384 -> 256 (h output) ----
    bgemm_kernel<3, 1><<<dim3(2, gy), 256>>>(nullptr, OFF4, nullptr, M, 384, 256);
    bgemm_kernel<3, 2><<<dim3(2, gy), 256>>>(nullptr, WSEG + OFF4, nullptr, M, 384, 256);
    combine_kernel<2, 0><<<NN, 128>>>(b4, out_h, 1);      // -> d_out h region

    // ---- Layer 5: 256 -> 5 (no relu) ----
    gemm_small_kernel<1><<<(NN * 5 + 255) / 256, 256>>>(out_h, Wl5, M, 256, 5);
    gemm_small_kernel<2><<<(NN * 5 + 255) / 256, 256>>>(out_h, Wr5, M, 256, 5);
    combine5_kernel<<<(NN + 3) / 4, 128>>>(b5, out_cls);
}

// round 6
// speedup vs baseline: 2.3583x; 1.4627x over previous
#include <cuda_runtime.h>
#include <cuda_bf16.h>
#include <cstdint>

#define NN 20000
#define EE 320000

// ================= static scratch =================
__device__ __align__(16) float g_A[NN * 1536];
__device__ __align__(16) float g_B[NN * 1536];
// bf16 hi/lo split activations (GEMM A-side input for every layer)
__device__ __align__(16) __nv_bfloat16 g_Hh[NN * 1536];
__device__ __align__(16) __nv_bfloat16 g_Hl[NN * 1536];
// bf16 transposed-split weights: [Wl layers 1-4 | Wr layers 1-4]
#define WSEG 2752512
__device__ __align__(16) __nv_bfloat16 g_Wh[2 * WSEG];
__device__ __align__(16) __nv_bfloat16 g_Wlo[2 * WSEG];
__device__ int   g_deg[NN];
__device__ int   g_fill[NN];
__device__ int   g_rowptr[NN + 1];
__device__ int   g_col[EE];
__device__ float g_dinv[NN];

// ================= helpers (baseline PTX, sm_80+) =================
__device__ __forceinline__ uint32_t smem_u32(const void* p) {
    uint32_t a;
    asm("{ .reg .u64 t; cvta.to.shared.u64 t, %1; cvt.u32.u64 %0, t; }" : "=r"(a) : "l"(p));
    return a;
}
__device__ __forceinline__ void ldm_x4(uint32_t* r, uint32_t addr) {
    asm volatile("ldmatrix.sync.aligned.m8n8.x4.shared.b16 {%0,%1,%2,%3}, [%4];"
        : "=r"(r[0]), "=r"(r[1]), "=r"(r[2]), "=r"(r[3]) : "r"(addr));
}
__device__ __forceinline__ void mma16816(float* c, const uint32_t* a, const uint32_t* b) {
    asm volatile("mma.sync.aligned.m16n8k16.row.col.f32.bf16.bf16.f32 "
        "{%0,%1,%2,%3}, {%4,%5,%6,%7}, {%8,%9}, {%0,%1,%2,%3};"
        : "+f"(c[0]), "+f"(c[1]), "+f"(c[2]), "+f"(c[3])
        : "r"(a[0]), "r"(a[1]), "r"(a[2]), "r"(a[3]), "r"(b[0]), "r"(b[1]));
}
__device__ __forceinline__ uint32_t sw128(uint32_t off) {
    return off ^ ((off >> 3) & 0x70);
}
#define CP_ASYNC16(saddr, gptr) \
    asm volatile("cp.async.cg.shared.global [%0], [%1], 16;" :: "r"(saddr), "l"(gptr))
#define CP_COMMIT() asm volatile("cp.async.commit_group;")
#define CP_WAIT1()  asm volatile("cp.async.wait_group 1;")

// ================= CSR construction (edge_index int32) =================
__global__ void zero_counts_kernel() {
    int i = blockIdx.x * blockDim.x + threadIdx.x;
    if (i < NN) { g_deg[i] = 0; g_fill[i] = 0; }
}
__global__ void count_deg_kernel(const int* __restrict__ ei) {
    int e = blockIdx.x * blockDim.x + threadIdx.x;
    if (e < EE) {
        int dst = ei[EE + e];
        if ((unsigned)dst < NN) atomicAdd(&g_deg[dst], 1);
    }
}
__global__ void scan_deg_kernel() {
    __shared__ int sh[1024];
    int tid = threadIdx.x;
    int carry = 0;
    if (tid == 0) g_rowptr[0] = 0;
    for (int base = 0; base < NN; base += 1024) {
        int i = base + tid;
        int v = (i < NN) ? g_deg[i] : 0;
        sh[tid] = v;
        __syncthreads();
        for (int off = 1; off < 1024; off <<= 1) {
            int t = (tid >= off) ? sh[tid - off] : 0;
            __syncthreads();
            sh[tid] += t;
            __syncthreads();
        }
        if (i < NN) {
            g_rowptr[i + 1] = carry + sh[tid];
            g_dinv[i] = 1.0f / fmaxf((float)v, 1.0f);
        }
        int last = sh[1023];
        __syncthreads();
        carry += last;
    }
}
__global__ void fill_csr_kernel(const int* __restrict__ ei) {
    int e = blockIdx.x * blockDim.x + threadIdx.x;
    if (e < EE) {
        int src = ei[e];
        int dst = ei[EE + e];
        if ((unsigned)dst < NN && (unsigned)src < NN) {
            int p = atomicAdd(&g_fill[dst], 1);
            g_col[g_rowptr[dst] + p] = src;
        }
    }
}

// ================= weight prep: transpose + bf16 hi/lo split =================
__global__ void wprep_kernel(const float* __restrict__ W, int K, int N, int off) {
    int idx = blockIdx.x * blockDim.x + threadIdx.x;
    if (idx >= K * N) return;
    int n = idx / K, k = idx - n * K;
    float w = W[(size_t)k * N + n];
    __nv_bfloat16 hi = __float2bfloat16(w);
    float lo = w - __bfloat162float(hi);
    g_Wh[off + idx] = hi;
    g_Wlo[off + idx] = __float2bfloat16(lo);
}

// split input x into bf16 hi/lo activation buffers
__global__ void split_x_kernel(const float* __restrict__ x, int total) {
    int idx = blockIdx.x * blockDim.x + threadIdx.x;
    if (idx >= total) return;
    float w = x[idx];
    __nv_bfloat16 hi = __float2bfloat16(w);
    g_Hh[idx] = hi;
    g_Hl[idx] = __float2bfloat16(w - __bfloat162float(hi));
}

// ================= HMMA GEMM v2: C = H @ W =================
// A from g_Hh/g_Hl [M][Kd] bf16, W pre-transposed+split [Nd][Kd] at woff (+z*WSEG).
// C = z ? g_B : g_A. 3-term split: D = Ah*Wh + Ah*Wl + Al*Wh.
// BM=BN=128, BK=64, 256 threads, 8 warps (2m x 4n), warp tile 64x32.
// 2-stage cp.async pipeline; per stage: sAh|sAl|sBh|sBl each 128 rows x 128B.
#define STG 65536
__global__ __launch_bounds__(256) void bgemm2_kernel(int woff_base, int M, int Kd, int Nd)
{
    extern __shared__ __align__(1024) uint8_t dsm[];
    const int tid = threadIdx.x;
    const int wid = tid >> 5;
    const int lane = tid & 31;
    const int m0 = blockIdx.y * 128;
    const int n0 = blockIdx.x * 128;
    const int woff = woff_base + blockIdx.z * WSEG;
    float* C = blockIdx.z ? g_B : g_A;
    const int warp_m = (wid & 1) * 64;
    const int warp_n = (wid >> 1) * 32;
    const uint32_t sb = smem_u32(dsm);

    // per-thread load coords: row 0..127, q = k-half (32 elems = 64B)
    const int lrow = tid >> 1;
    const int q = tid & 1;
    const int arow = min(m0 + lrow, M - 1);   // clamp; extra rows masked at store
    const __nv_bfloat16* gAh = g_Hh + (size_t)arow * Kd + q * 32;
    const __nv_bfloat16* gAl = g_Hl + (size_t)arow * Kd + q * 32;
    const __nv_bfloat16* gBh = g_Wh + woff + (size_t)(n0 + lrow) * Kd + q * 32;
    const __nv_bfloat16* gBl = g_Wlo + woff + (size_t)(n0 + lrow) * Kd + q * 32;
    const uint32_t dbase = lrow * 128 + q * 64;

    float acc[4][4][4];
#pragma unroll
    for (int mi = 0; mi < 4; mi++)
#pragma unroll
        for (int ni = 0; ni < 4; ni++)
#pragma unroll
            for (int qq = 0; qq < 4; qq++) acc[mi][ni][qq] = 0.f;

    const int sub = lane >> 3;
    const int lr = lane & 7;
    const int nch = Kd >> 6;

    // prologue: stage 0
    {
        uint32_t s0 = sb;
#pragma unroll
        for (int j = 0; j < 4; j++) {
            uint32_t o = sw128(dbase + j * 16);
            CP_ASYNC16(s0 + o,         gAh + j * 8);
            CP_ASYNC16(s0 + 16384 + o, gAl + j * 8);
            CP_ASYNC16(s0 + 32768 + o, gBh + j * 8);
            CP_ASYNC16(s0 + 49152 + o, gBl + j * 8);
        }
        CP_COMMIT();
    }

    for (int ch = 0; ch < nch; ch++) {
        const int s = ch & 1;
        if (ch + 1 < nch) {
            const int k1 = (ch + 1) << 6;
            uint32_t s1 = sb + (s ^ 1) * STG;
#pragma unroll
            for (int j = 0; j < 4; j++) {
                uint32_t o = sw128(dbase + j * 16);
                CP_ASYNC16(s1 + o,         gAh + k1 + j * 8);
                CP_ASYNC16(s1 + 16384 + o, gAl + k1 + j * 8);
                CP_ASYNC16(s1 + 32768 + o, gBh + k1 + j * 8);
                CP_ASYNC16(s1 + 49152 + o, gBl + k1 + j * 8);
            }
        }
        CP_COMMIT();
        CP_WAIT1();
        __syncthreads();

        const uint32_t sAh = sb + s * STG;
        const uint32_t sAl = sAh + 16384;
        const uint32_t sBh = sAh + 32768;
        const uint32_t sBl = sAh + 49152;

#pragma unroll
        for (int ks = 0; ks < 4; ks++) {
            uint32_t ah[4][4], al[4][4];
#pragma unroll
            for (int mi = 0; mi < 4; mi++) {
                int row = warp_m + mi * 16 + (sub & 1) * 8 + lr;
                uint32_t kb = ks * 32 + (sub >> 1) * 16;
                uint32_t o = sw128(row * 128 + kb);
                ldm_x4(ah[mi], sAh + o);
                ldm_x4(al[mi], sAl + o);
            }
            uint32_t bh[2][4], bl[2][4];
#pragma unroll
            for (int np = 0; np < 2; np++) {
                int row = warp_n + np * 16 + (sub >> 1) * 8 + lr;
                uint32_t kb = ks * 32 + (sub & 1) * 16;
                uint32_t o = sw128(row * 128 + kb);
                ldm_x4(bh[np], sBh + o);
                ldm_x4(bl[np], sBl + o);
            }
#pragma unroll
            for (int mi = 0; mi < 4; mi++)
#pragma unroll
                for (int ni = 0; ni < 4; ni++) {
                    const uint32_t* ph = &bh[ni >> 1][(ni & 1) * 2];
                    const uint32_t* pl = &bl[ni >> 1][(ni & 1) * 2];
                    mma16816(acc[mi][ni], ah[mi], ph);
                    mma16816(acc[mi][ni], ah[mi], pl);
                    mma16816(acc[mi][ni], al[mi], ph);
                }
        }
        __syncthreads();
    }

    // ---- epilogue ----
    const int g = lane >> 2;
    const int t = lane & 3;
#pragma unroll
    for (int mi = 0; mi < 4; mi++) {
        int r0 = m0 + warp_m + mi * 16 + g;
        int r1 = r0 + 8;
#pragma unroll
        for (int ni = 0; ni < 4; ni++) {
            int col = n0 + warp_n + ni * 8 + t * 2;
            if (r0 < M) *(float2*)(C + (size_t)r0 * Nd + col) = make_float2(acc[mi][ni][0], acc[mi][ni][1]);
            if (r1 < M) *(float2*)(C + (size_t)r1 * Nd + col) = make_float2(acc[mi][ni][2], acc[mi][ni][3]);
        }
    }
}

// ================= small-N GEMM for the final 256->5 linear =================
__global__ void gemm_small_kernel(const float* __restrict__ Aext,
                                  const float* __restrict__ W,
                                  int zsel, int M, int Kd, int Nd)
{
    float* C = zsel ? g_B : g_A;
    int idx = blockIdx.x * blockDim.x + threadIdx.x;
    if (idx >= M * Nd) return;
    int row = idx / Nd, c = idx % Nd;
    const float* a = Aext + (size_t)row * Kd;
    float acc = 0.f;
    for (int k = 0; k < Kd; k++) acc += a[k] * W[k * Nd + c];
    C[idx] = acc;
}

// ================= combine: r = relu(deg_inv * agg(g_A) + g_B + bias) ====
// SPLIT=1: write bf16 hi/lo to g_Hh/g_Hl (next layer GEMM input).
// SPLIT=0: write fp32 to outExt.
template <int VPT, int SPLIT>
__global__ __launch_bounds__(128) void combine_kernel(
    const float* __restrict__ bias, float* __restrict__ outExt)
{
    const int node = blockIdx.x;
    const int tid = threadIdx.x;
    const int F = VPT * 128;
    const int s = g_rowptr[node];
    const int e = g_rowptr[node + 1];

    float acc[VPT];
#pragma unroll
    for (int v = 0; v < VPT; v++) acc[v] = 0.f;

    __shared__ int nb[128];
    for (int base = s; base < e; base += 128) {
        int cnt = min(128, e - base);
        if (tid < cnt) nb[tid] = g_col[base + tid];
        __syncthreads();
        for (int j = 0; j < cnt; j++) {
            const float* row = g_A + (size_t)nb[j] * F;
#pragma unroll
            for (int v = 0; v < VPT; v++) acc[v] += row[tid + v * 128];
        }
        __syncthreads();
    }

    const float di = g_dinv[node];
#pragma unroll
    for (int v = 0; v < VPT; v++) {
        int c = tid + v * 128;
        float r = acc[v] * di + g_B[(size_t)node * F + c] + bias[c];
        r = fmaxf(r, 0.f);
        if constexpr (SPLIT) {
            __nv_bfloat16 hi = __float2bfloat16(r);
            g_Hh[(size_t)node * F + c] = hi;
            g_Hl[(size_t)node * F + c] = __float2bfloat16(r - __bfloat162float(hi));
        } else {
            outExt[(size_t)node * F + c] = r;
        }
    }
}

__global__ void combine5_kernel(const float* __restrict__ bias,
                                float* __restrict__ out)
{
    int node = blockIdx.x * 4 + (threadIdx.x >> 5);
    if (node >= NN) return;
    int lane = threadIdx.x & 31;
    if (lane >= 5) return;
    int s = g_rowptr[node], e = g_rowptr[node + 1];
    float acc = 0.f;
    for (int j = s; j < e; j++) acc += g_A[g_col[j] * 5 + lane];
    out[node * 5 + lane] = acc * g_dinv[node] + g_B[node * 5 + lane] + bias[lane];
}

// ================= launch =================
extern "C" void kernel_launch(void* const* d_in, const int* in_sizes, int n_in,
                              void* d_out, int out_size)
{
    const float* x  = (const float*)d_in[0];
    const int*   ei = (const int*)d_in[1];
    const float* Wl1 = (const float*)d_in[2];
    const float* Wr1 = (const float*)d_in[3];
    const float* b1  = (const float*)d_in[4];
    const float* Wl2 = (const float*)d_in[5];
    const float* Wr2 = (const float*)d_in[6];
    const float* b2  = (const float*)d_in[7];
    const float* Wl3 = (const float*)d_in[8];
    const float* Wr3 = (const float*)d_in[9];
    const float* b3  = (const float*)d_in[10];
    const float* Wl4 = (const float*)d_in[11];
    const float* Wr4 = (const float*)d_in[12];
    const float* b4  = (const float*)d_in[13];
    const float* Wl5 = (const float*)d_in[14];
    const float* Wr5 = (const float*)d_in[15];
    const float* b5  = (const float*)d_in[16];

    float* out = (float*)d_out;
    float* out_h   = out;                      // [NN, 256]
    float* out_cls = out + (size_t)NN * 256;   // [NN, 5]

    cudaFuncSetAttribute(bgemm2_kernel, cudaFuncAttributeMaxDynamicSharedMemorySize, 2 * STG);

    // ---- CSR build ----
    zero_counts_kernel<<<(NN + 255) / 256, 256>>>();
    count_deg_kernel<<<(EE + 255) / 256, 256>>>(ei);
    scan_deg_kernel<<<1, 1024>>>();
    fill_csr_kernel<<<(EE + 255) / 256, 256>>>(ei);

    // ---- weight prep + input split ----
    const int OFF1 = 0, OFF2 = 1179648, OFF3 = 2359296, OFF4 = 2654208;
    wprep_kernel<<<(768 * 1536 + 255) / 256, 256>>>(Wl1, 768, 1536, OFF1);
    wprep_kernel<<<(1536 * 768 + 255) / 256, 256>>>(Wl2, 1536, 768, OFF2);
    wprep_kernel<<<(768 * 384 + 255) / 256, 256>>>(Wl3, 768, 384, OFF3);
    wprep_kernel<<<(384 * 256 + 255) / 256, 256>>>(Wl4, 384, 256, OFF4);
    wprep_kernel<<<(768 * 1536 + 255) / 256, 256>>>(Wr1, 768, 1536, WSEG + OFF1);
    wprep_kernel<<<(1536 * 768 + 255) / 256, 256>>>(Wr2, 1536, 768, WSEG + OFF2);
    wprep_kernel<<<(768 * 384 + 255) / 256, 256>>>(Wr3, 768, 384, WSEG + OFF3);
    wprep_kernel<<<(384 * 256 + 255) / 256, 256>>>(Wr4, 384, 256, WSEG + OFF4);
    split_x_kernel<<<(NN * 768 + 255) / 256, 256>>>(x, NN * 768);

    const int M = NN;
    const int gy = (M + 127) / 128;   // 157

    // ---- Layer 1: 768 -> 1536 ----
    bgemm2_kernel<<<dim3(12, gy, 2), 256, 2 * STG>>>(OFF1, M, 768, 1536);
    combine_kernel<12, 1><<<NN, 128>>>(b1, nullptr);      // -> g_Hh/g_Hl

    // ---- Layer 2: 1536 -> 768 ----
    bgemm2_kernel<<<dim3(6, gy, 2), 256, 2 * STG>>>(OFF2, M, 1536, 768);
    combine_kernel<6, 1><<<NN, 128>>>(b2, nullptr);       // -> g_Hh/g_Hl

    // ---- Layer 3: 768 -> 384 ----
    bgemm2_kernel<<<dim3(3, gy, 2), 256, 2 * STG>>>(OFF3, M, 768, 384);
    combine_kernel<3, 1><<<NN, 128>>>(b3, nullptr);       // -> g_Hh/g_Hl

    // ---- Layer 4: 384 -> 256 (h output, fp32) ----
    bgemm2_kernel<<<dim3(2, gy, 2), 256, 2 * STG>>>(OFF4, M, 384, 256);
    combine_kernel<2, 0><<<NN, 128>>>(b4, out_h);         // -> d_out h region

    // ---- Layer 5: 256 -> 5 (no relu) ----
    gemm_small_kernel<<<(NN * 5 + 255) / 256, 256>>>(out_h, Wl5, 0, M, 256, 5);
    gemm_small_kernel<<<(NN * 5 + 255) / 256, 256>>>(out_h, Wr5, 1, M, 256, 5);
    combine5_kernel<<<(NN + 3) / 4, 128>>>(b5, out_cls);
}

// round 7
// speedup vs baseline: 2.5272x; 1.0716x over previous
#include <cuda_runtime.h>
#include <cuda_bf16.h>
#include <cstdint>

#define NN 20000
#define EE 320000

// ================= static scratch =================
__device__ __align__(16) float g_A[NN * 1536];    // GEMM fp32 out (z=0)
__device__ __align__(16) float g_B[NN * 1536];    // GEMM fp32 out (z=1)
// bf16 hi/lo split activation buffers (ping-pong)
__device__ __align__(16) __nv_bfloat16 g_Hh[NN * 1536];
__device__ __align__(16) __nv_bfloat16 g_Hl[NN * 1536];
__device__ __align__(16) __nv_bfloat16 g_H2h[NN * 1536];
__device__ __align__(16) __nv_bfloat16 g_H2l[NN * 1536];
// bf16 transposed-split weights, manual offsets (total 5505024 elems)
__device__ __align__(16) __nv_bfloat16 g_Wh[5505024];
__device__ __align__(16) __nv_bfloat16 g_Wlo[5505024];
__device__ int   g_deg[NN];
__device__ int   g_fill[NN];
__device__ int   g_rowptr[NN + 1];
__device__ int   g_col[EE];
__device__ float g_dinv[NN];

// ================= helpers (baseline PTX, sm_80+) =================
__device__ __forceinline__ uint32_t smem_u32(const void* p) {
    uint32_t a;
    asm("{ .reg .u64 t; cvta.to.shared.u64 t, %1; cvt.u32.u64 %0, t; }" : "=r"(a) : "l"(p));
    return a;
}
__device__ __forceinline__ void ldm_x4(uint32_t* r, uint32_t addr) {
    asm volatile("ldmatrix.sync.aligned.m8n8.x4.shared.b16 {%0,%1,%2,%3}, [%4];"
        : "=r"(r[0]), "=r"(r[1]), "=r"(r[2]), "=r"(r[3]) : "r"(addr));
}
__device__ __forceinline__ void mma16816(float* c, const uint32_t* a, const uint32_t* b) {
    asm volatile("mma.sync.aligned.m16n8k16.row.col.f32.bf16.bf16.f32 "
        "{%0,%1,%2,%3}, {%4,%5,%6,%7}, {%8,%9}, {%0,%1,%2,%3};"
        : "+f"(c[0]), "+f"(c[1]), "+f"(c[2]), "+f"(c[3])
        : "r"(a[0]), "r"(a[1]), "r"(a[2]), "r"(a[3]), "r"(b[0]), "r"(b[1]));
}
__device__ __forceinline__ uint32_t sw128(uint32_t off) {
    return off ^ ((off >> 3) & 0x70);
}
__device__ __forceinline__ uint32_t pack_bf2(float a, float b) {
    __nv_bfloat162 v = __halves2bfloat162(__float2bfloat16(a), __float2bfloat16(b));
    return *(uint32_t*)&v;
}
#define CP_ASYNC16(saddr, gptr) \
    asm volatile("cp.async.cg.shared.global [%0], [%1], 16;" :: "r"(saddr), "l"(gptr))
#define CP_COMMIT() asm volatile("cp.async.commit_group;")
#define CP_WAIT1()  asm volatile("cp.async.wait_group 1;")

// ================= CSR construction (edge_index int32) =================
__global__ void zero_counts_kernel() {
    int i = blockIdx.x * blockDim.x + threadIdx.x;
    if (i < NN) { g_deg[i] = 0; g_fill[i] = 0; }
}
__global__ void count_deg_kernel(const int* __restrict__ ei) {
    int e = blockIdx.x * blockDim.x + threadIdx.x;
    if (e < EE) {
        int dst = ei[EE + e];
        if ((unsigned)dst < NN) atomicAdd(&g_deg[dst], 1);
    }
}
__global__ void scan_deg_kernel() {
    __shared__ int sh[1024];
    int tid = threadIdx.x;
    int carry = 0;
    if (tid == 0) g_rowptr[0] = 0;
    for (int base = 0; base < NN; base += 1024) {
        int i = base + tid;
        int v = (i < NN) ? g_deg[i] : 0;
        sh[tid] = v;
        __syncthreads();
        for (int off = 1; off < 1024; off <<= 1) {
            int t = (tid >= off) ? sh[tid - off] : 0;
            __syncthreads();
            sh[tid] += t;
            __syncthreads();
        }
        if (i < NN) {
            g_rowptr[i + 1] = carry + sh[tid];
            g_dinv[i] = 1.0f / fmaxf((float)v, 1.0f);
        }
        int last = sh[1023];
        __syncthreads();
        carry += last;
    }
}
__global__ void fill_csr_kernel(const int* __restrict__ ei) {
    int e = blockIdx.x * blockDim.x + threadIdx.x;
    if (e < EE) {
        int src = ei[e];
        int dst = ei[EE + e];
        if ((unsigned)dst < NN && (unsigned)src < NN) {
            int p = atomicAdd(&g_fill[dst], 1);
            g_col[g_rowptr[dst] + p] = src;
        }
    }
}

// ================= weight prep: transpose + bf16 hi/lo split =================
// dest[off + n*K2 + kofs + k] = split(W[k*N + n])
__global__ void wprep_kernel(const float* __restrict__ W, int K, int N,
                             int off, int kofs, int K2) {
    int idx = blockIdx.x * blockDim.x + threadIdx.x;
    if (idx >= K * N) return;
    int n = idx / K, k = idx - n * K;
    float w = W[(size_t)k * N + n];
    __nv_bfloat16 hi = __float2bfloat16(w);
    float lo = w - __bfloat162float(hi);
    size_t d = (size_t)off + (size_t)n * K2 + kofs + k;
    g_Wh[d] = hi;
    g_Wlo[d] = __float2bfloat16(lo);
}

// split x into cols [768..1535] of buf0 rows (stride 1536)
__global__ void split_x_kernel(const float* __restrict__ x) {
    int idx = blockIdx.x * blockDim.x + threadIdx.x;
    if (idx >= NN * 768) return;
    int n = idx / 768, c = idx - n * 768;
    float w = x[idx];
    __nv_bfloat16 hi = __float2bfloat16(w);
    size_t d = (size_t)n * 1536 + 768 + c;
    g_Hh[d] = hi;
    g_Hl[d] = __float2bfloat16(w - __bfloat162float(hi));
}

// mean-aggregate x rows -> split -> cols [0..767] of buf0 rows (stride 1536)
__global__ __launch_bounds__(192) void aggx_kernel(const float* __restrict__ x) {
    const int node = blockIdx.x;
    const int tid = threadIdx.x;   // 0..191, one float4 slot each
    const int s = g_rowptr[node];
    const int e = g_rowptr[node + 1];
    float4 acc = make_float4(0.f, 0.f, 0.f, 0.f);
    __shared__ int nb[192];
    for (int base = s; base < e; base += 192) {
        int cnt = min(192, e - base);
        if (tid < cnt) nb[tid] = g_col[base + tid];
        __syncthreads();
        for (int j = 0; j < cnt; j++) {
            float4 v = ((const float4*)(x + (size_t)nb[j] * 768))[tid];
            acc.x += v.x; acc.y += v.y; acc.z += v.z; acc.w += v.w;
        }
        __syncthreads();
    }
    const float di = g_dinv[node];
    acc.x *= di; acc.y *= di; acc.z *= di; acc.w *= di;
    // split + write 4 bf16 (8B)
    float hx = __bfloat162float(__float2bfloat16(acc.x));
    float hy = __bfloat162float(__float2bfloat16(acc.y));
    float hz = __bfloat162float(__float2bfloat16(acc.z));
    float hw = __bfloat162float(__float2bfloat16(acc.w));
    uint2 hp = make_uint2(pack_bf2(acc.x, acc.y), pack_bf2(acc.z, acc.w));
    uint2 lp = make_uint2(pack_bf2(acc.x - hx, acc.y - hy), pack_bf2(acc.z - hz, acc.w - hw));
    size_t d = (size_t)node * 1536 + tid * 4;
    *(uint2*)(g_Hh + d) = hp;
    *(uint2*)(g_Hl + d) = lp;
}

// ================= HMMA GEMM =================
// AB: 0 -> A from g_Hh/g_Hl, 1 -> A from g_H2h/g_H2l
// EPI: 0 -> fp32 out to (z ? g_B : g_A); gridDim.z = 2, weights woff_l/woff_r
// EPI: 1 -> fused bias+relu+split out to the OTHER buffer pair; gridDim.z = 1
#define STG 65536
template <int AB, int EPI>
__global__ __launch_bounds__(256) void bgemm_kernel(
    int woff_l, int woff_r, const float* __restrict__ bias,
    int M, int Kd, int Nd)
{
    extern __shared__ __align__(1024) uint8_t dsm[];
    const __nv_bfloat16* Ah = AB ? g_H2h : g_Hh;
    const __nv_bfloat16* Al = AB ? g_H2l : g_Hl;
    const int tid = threadIdx.x;
    const int wid = tid >> 5;
    const int lane = tid & 31;
    const int m0 = blockIdx.y * 128;
    const int n0 = blockIdx.x * 128;
    const int woff = blockIdx.z ? woff_r : woff_l;
    const int warp_m = (wid & 1) * 64;
    const int warp_n = (wid >> 1) * 32;
    const uint32_t sb = smem_u32(dsm);

    const int lrow = tid >> 1;
    const int q = tid & 1;
    const int arow = min(m0 + lrow, M - 1);
    const __nv_bfloat16* gAh = Ah + (size_t)arow * Kd + q * 32;
    const __nv_bfloat16* gAl = Al + (size_t)arow * Kd + q * 32;
    const __nv_bfloat16* gBh = g_Wh + woff + (size_t)(n0 + lrow) * Kd + q * 32;
    const __nv_bfloat16* gBl = g_Wlo + woff + (size_t)(n0 + lrow) * Kd + q * 32;
    const uint32_t dbase = lrow * 128 + q * 64;

    float acc[4][4][4];
#pragma unroll
    for (int mi = 0; mi < 4; mi++)
#pragma unroll
        for (int ni = 0; ni < 4; ni++)
#pragma unroll
            for (int qq = 0; qq < 4; qq++) acc[mi][ni][qq] = 0.f;

    const int sub = lane >> 3;
    const int lr = lane & 7;
    const int nch = Kd >> 6;

    {
        uint32_t s0 = sb;
#pragma unroll
        for (int j = 0; j < 4; j++) {
            uint32_t o = sw128(dbase + j * 16);
            CP_ASYNC16(s0 + o,         gAh + j * 8);
            CP_ASYNC16(s0 + 16384 + o, gAl + j * 8);
            CP_ASYNC16(s0 + 32768 + o, gBh + j * 8);
            CP_ASYNC16(s0 + 49152 + o, gBl + j * 8);
        }
        CP_COMMIT();
    }

    for (int ch = 0; ch < nch; ch++) {
        const int s = ch & 1;
        if (ch + 1 < nch) {
            const int k1 = (ch + 1) << 6;
            uint32_t s1 = sb + (s ^ 1) * STG;
#pragma unroll
            for (int j = 0; j < 4; j++) {
                uint32_t o = sw128(dbase + j * 16);
                CP_ASYNC16(s1 + o,         gAh + k1 + j * 8);
                CP_ASYNC16(s1 + 16384 + o, gAl + k1 + j * 8);
                CP_ASYNC16(s1 + 32768 + o, gBh + k1 + j * 8);
                CP_ASYNC16(s1 + 49152 + o, gBl + k1 + j * 8);
            }
        }
        CP_COMMIT();
        CP_WAIT1();
        __syncthreads();

        const uint32_t sAh = sb + s * STG;
        const uint32_t sAl = sAh + 16384;
        const uint32_t sBh = sAh + 32768;
        const uint32_t sBl = sAh + 49152;

#pragma unroll
        for (int ks = 0; ks < 4; ks++) {
            uint32_t ah[4][4], al[4][4];
#pragma unroll
            for (int mi = 0; mi < 4; mi++) {
                int row = warp_m + mi * 16 + (sub & 1) * 8 + lr;
                uint32_t kb = ks * 32 + (sub >> 1) * 16;
                uint32_t o = sw128(row * 128 + kb);
                ldm_x4(ah[mi], sAh + o);
                ldm_x4(al[mi], sAl + o);
            }
            uint32_t bh[2][4], bl[2][4];
#pragma unroll
            for (int np = 0; np < 2; np++) {
                int row = warp_n + np * 16 + (sub >> 1) * 8 + lr;
                uint32_t kb = ks * 32 + (sub & 1) * 16;
                uint32_t o = sw128(row * 128 + kb);
                ldm_x4(bh[np], sBh + o);
                ldm_x4(bl[np], sBl + o);
            }
#pragma unroll
            for (int mi = 0; mi < 4; mi++)
#pragma unroll
                for (int ni = 0; ni < 4; ni++) {
                    const uint32_t* ph = &bh[ni >> 1][(ni & 1) * 2];
                    const uint32_t* pl = &bl[ni >> 1][(ni & 1) * 2];
                    mma16816(acc[mi][ni], ah[mi], ph);
                    mma16816(acc[mi][ni], ah[mi], pl);
                    mma16816(acc[mi][ni], al[mi], ph);
                }
        }
        __syncthreads();
    }

    // ---- epilogue ----
    const int g = lane >> 2;
    const int t = lane & 3;
    if constexpr (EPI == 0) {
        float* C = blockIdx.z ? g_B : g_A;
#pragma unroll
        for (int mi = 0; mi < 4; mi++) {
            int r0 = m0 + warp_m + mi * 16 + g;
            int r1 = r0 + 8;
#pragma unroll
            for (int ni = 0; ni < 4; ni++) {
                int col = n0 + warp_n + ni * 8 + t * 2;
                if (r0 < M) *(float2*)(C + (size_t)r0 * Nd + col) = make_float2(acc[mi][ni][0], acc[mi][ni][1]);
                if (r1 < M) *(float2*)(C + (size_t)r1 * Nd + col) = make_float2(acc[mi][ni][2], acc[mi][ni][3]);
            }
        }
    } else {
        __nv_bfloat16* Oh = AB ? g_Hh : g_H2h;
        __nv_bfloat16* Ol = AB ? g_Hl : g_H2l;
#pragma unroll
        for (int mi = 0; mi < 4; mi++) {
            int r0 = m0 + warp_m + mi * 16 + g;
            int r1 = r0 + 8;
#pragma unroll
            for (int ni = 0; ni < 4; ni++) {
                int col = n0 + warp_n + ni * 8 + t * 2;
                float b0 = bias[col], b1v = bias[col + 1];
                float v0 = fmaxf(acc[mi][ni][0] + b0, 0.f);
                float v1 = fmaxf(acc[mi][ni][1] + b1v, 0.f);
                float v2 = fmaxf(acc[mi][ni][2] + b0, 0.f);
                float v3 = fmaxf(acc[mi][ni][3] + b1v, 0.f);
                float h0 = __bfloat162float(__float2bfloat16(v0));
                float h1 = __bfloat162float(__float2bfloat16(v1));
                float h2 = __bfloat162float(__float2bfloat16(v2));
                float h3 = __bfloat162float(__float2bfloat16(v3));
                if (r0 < M) {
                    *(uint32_t*)(Oh + (size_t)r0 * Nd + col) = pack_bf2(v0, v1);
                    *(uint32_t*)(Ol + (size_t)r0 * Nd + col) = pack_bf2(v0 - h0, v1 - h1);
                }
                if (r1 < M) {
                    *(uint32_t*)(Oh + (size_t)r1 * Nd + col) = pack_bf2(v2, v3);
                    *(uint32_t*)(Ol + (size_t)r1 * Nd + col) = pack_bf2(v2 - h2, v3 - h3);
                }
            }
        }
    }
}

// ================= small-N GEMM for the final 256->5 linear =================
__global__ void gemm_small_kernel(const float* __restrict__ Aext,
                                  const float* __restrict__ W,
                                  int zsel, int M, int Kd, int Nd)
{
    float* C = zsel ? g_B : g_A;
    int idx = blockIdx.x * blockDim.x + threadIdx.x;
    if (idx >= M * Nd) return;
    int row = idx / Nd, c = idx % Nd;
    const float* a = Aext + (size_t)row * Kd;
    float acc = 0.f;
    for (int k = 0; k < Kd; k++) acc += a[k] * W[k * Nd + c];
    C[idx] = acc;
}

// ================= combine (layers 2-4): r = relu(di*agg(g_A) + g_B + b) ===
// NT = F/4 threads, one float4 per thread.
// OM: 0 -> fp32 float4 to ext; 1 -> split to buf0; 2 -> split to buf1
template <int F, int OM>
__global__ void combine_kernel(const float* __restrict__ bias,
                               float* __restrict__ outExt)
{
    constexpr int NT = F / 4;
    const int node = blockIdx.x;
    const int tid = threadIdx.x;
    const int s = g_rowptr[node];
    const int e = g_rowptr[node + 1];

    float4 acc = make_float4(0.f, 0.f, 0.f, 0.f);
    __shared__ int nb[NT];
    for (int base = s; base < e; base += NT) {
        int cnt = min(NT, e - base);
        if (tid < cnt) nb[tid] = g_col[base + tid];
        __syncthreads();
        for (int j = 0; j < cnt; j++) {
            float4 v = ((const float4*)(g_A + (size_t)nb[j] * F))[tid];
            acc.x += v.x; acc.y += v.y; acc.z += v.z; acc.w += v.w;
        }
        __syncthreads();
    }

    const float di = g_dinv[node];
    float4 sv = ((const float4*)(g_B + (size_t)node * F))[tid];
    float4 bv = ((const float4*)bias)[tid];
    float rx = fmaxf(acc.x * di + sv.x + bv.x, 0.f);
    float ry = fmaxf(acc.y * di + sv.y + bv.y, 0.f);
    float rz = fmaxf(acc.z * di + sv.z + bv.z, 0.f);
    float rw = fmaxf(acc.w * di + sv.w + bv.w, 0.f);

    if constexpr (OM == 0) {
        ((float4*)(outExt + (size_t)node * F))[tid] = make_float4(rx, ry, rz, rw);
    } else {
        __nv_bfloat16* Oh = (OM == 1) ? g_Hh : g_H2h;
        __nv_bfloat16* Ol = (OM == 1) ? g_Hl : g_H2l;
        float hx = __bfloat162float(__float2bfloat16(rx));
        float hy = __bfloat162float(__float2bfloat16(ry));
        float hz = __bfloat162float(__float2bfloat16(rz));
        float hw = __bfloat162float(__float2bfloat16(rw));
        size_t d = (size_t)node * F + tid * 4;
        *(uint2*)(Oh + d) = make_uint2(pack_bf2(rx, ry), pack_bf2(rz, rw));
        *(uint2*)(Ol + d) = make_uint2(pack_bf2(rx - hx, ry - hy), pack_bf2(rz - hz, rw - hw));
    }
}

__global__ void combine5_kernel(const float* __restrict__ bias,
                                float* __restrict__ out)
{
    int node = blockIdx.x * 4 + (threadIdx.x >> 5);
    if (node >= NN) return;
    int lane = threadIdx.x & 31;
    if (lane >= 5) return;
    int s = g_rowptr[node], e = g_rowptr[node + 1];
    float acc = 0.f;
    for (int j = s; j < e; j++) acc += g_A[g_col[j] * 5 + lane];
    out[node * 5 + lane] = acc * g_dinv[node] + g_B[node * 5 + lane] + bias[lane];
}

// ================= launch =================
extern "C" void kernel_launch(void* const* d_in, const int* in_sizes, int n_in,
                              void* d_out, int out_size)
{
    const float* x  = (const float*)d_in[0];
    const int*   ei = (const int*)d_in[1];
    const float* Wl1 = (const float*)d_in[2];
    const float* Wr1 = (const float*)d_in[3];
    const float* b1  = (const float*)d_in[4];
    const float* Wl2 = (const float*)d_in[5];
    const float* Wr2 = (const float*)d_in[6];
    const float* b2  = (const float*)d_in[7];
    const float* Wl3 = (const float*)d_in[8];
    const float* Wr3 = (const float*)d_in[9];
    const float* b3  = (const float*)d_in[10];
    const float* Wl4 = (const float*)d_in[11];
    const float* Wr4 = (const float*)d_in[12];
    const float* b4  = (const float*)d_in[13];
    const float* Wl5 = (const float*)d_in[14];
    const float* Wr5 = (const float*)d_in[15];
    const float* b5  = (const float*)d_in[16];

    float* out = (float*)d_out;
    float* out_h   = out;                      // [NN, 256]
    float* out_cls = out + (size_t)NN * 256;   // [NN, 5]

    cudaFuncSetAttribute(bgemm_kernel<0, 1>, cudaFuncAttributeMaxDynamicSharedMemorySize, 2 * STG);
    cudaFuncSetAttribute(bgemm_kernel<1, 0>, cudaFuncAttributeMaxDynamicSharedMemorySize, 2 * STG);
    cudaFuncSetAttribute(bgemm_kernel<0, 0>, cudaFuncAttributeMaxDynamicSharedMemorySize, 2 * STG);

    // ---- CSR build ----
    zero_counts_kernel<<<(NN + 255) / 256, 256>>>();
    count_deg_kernel<<<(EE + 255) / 256, 256>>>(ei);
    scan_deg_kernel<<<1, 1024>>>();
    fill_csr_kernel<<<(EE + 255) / 256, 256>>>(ei);

    // ---- weight prep ----
    // L1 concatenated: Wcat[1536][1536] = [[Wl1],[Wr1]]^T
    const int OFF1 = 0;
    const int OFF2L = 2359296, OFF2R = 3538944;
    const int OFF3L = 4718592, OFF3R = 5013504;
    const int OFF4L = 5308416, OFF4R = 5406720;
    wprep_kernel<<<(768 * 1536 + 255) / 256, 256>>>(Wl1, 768, 1536, OFF1, 0, 1536);
    wprep_kernel<<<(768 * 1536 + 255) / 256, 256>>>(Wr1, 768, 1536, OFF1, 768, 1536);
    wprep_kernel<<<(1536 * 768 + 255) / 256, 256>>>(Wl2, 1536, 768, OFF2L, 0, 1536);
    wprep_kernel<<<(1536 * 768 + 255) / 256, 256>>>(Wr2, 1536, 768, OFF2R, 0, 1536);
    wprep_kernel<<<(768 * 384 + 255) / 256, 256>>>(Wl3, 768, 384, OFF3L, 0, 768);
    wprep_kernel<<<(768 * 384 + 255) / 256, 256>>>(Wr3, 768, 384, OFF3R, 0, 768);
    wprep_kernel<<<(384 * 256 + 255) / 256, 256>>>(Wl4, 384, 256, OFF4L, 0, 384);
    wprep_kernel<<<(384 * 256 + 255) / 256, 256>>>(Wr4, 384, 256, OFF4R, 0, 384);

    // ---- input prep: x split (cols 768..1535) + agg(x) split (cols 0..767) ----
    split_x_kernel<<<(NN * 768 + 255) / 256, 256>>>(x);
    aggx_kernel<<<NN, 192>>>(x);

    const int M = NN;
    const int gy = (M + 127) / 128;   // 157

    // ---- Layer 1: fused [agg|x] @ [[Wl],[Wr]] (K=1536) + bias+relu+split ----
    bgemm_kernel<0, 1><<<dim3(12, gy, 1), 256, 2 * STG>>>(OFF1, OFF1, b1, M, 1536, 1536);  // -> buf1

    // ---- Layer 2: 1536 -> 768 ----
    bgemm_kernel<1, 0><<<dim3(6, gy, 2), 256, 2 * STG>>>(OFF2L, OFF2R, nullptr, M, 1536, 768);
    combine_kernel<768, 1><<<NN, 192>>>(b2, nullptr);     // -> buf0

    // ---- Layer 3: 768 -> 384 ----
    bgemm_kernel<0, 0><<<dim3(3, gy, 2), 256, 2 * STG>>>(OFF3L, OFF3R, nullptr, M, 768, 384);
    combine_kernel<384, 2><<<NN, 96>>>(b3, nullptr);      // -> buf1

    // ---- Layer 4: 384 -> 256 (h output fp32) ----
    bgemm_kernel<1, 0><<<dim3(2, gy, 2), 256, 2 * STG>>>(OFF4L, OFF4R, nullptr, M, 384, 256);
    combine_kernel<256, 0><<<NN, 64>>>(b4, out_h);        // -> d_out h region

    // ---- Layer 5: 256 -> 5 (no relu) ----
    gemm_small_kernel<<<(NN * 5 + 255) / 256, 256>>>(out_h, Wl5, 0, M, 256, 5);
    gemm_small_kernel<<<(NN * 5 + 255) / 256, 256>>>(out_h, Wr5, 1, M, 256, 5);
    combine5_kernel<<<(NN + 3) / 4, 128>>>(b5, out_cls);
}

// round 8
// speedup vs baseline: 2.5669x; 1.0157x over previous
#include <cuda_runtime.h>
#include <cuda_bf16.h>
#include <cstdint>

#define NN 20000
#define EE 320000

// ================= static scratch =================
__device__ __align__(16) float g_A[NN * 1536];    // GEMM fp32 out (z=0)
__device__ __align__(16) float g_B[NN * 1536];    // GEMM fp32 out (z=1)
// bf16 hi/lo split activation buffers (ping-pong)
__device__ __align__(16) __nv_bfloat16 g_Hh[NN * 1536];
__device__ __align__(16) __nv_bfloat16 g_Hl[NN * 1536];
__device__ __align__(16) __nv_bfloat16 g_H2h[NN * 1536];
__device__ __align__(16) __nv_bfloat16 g_H2l[NN * 1536];
// bf16 transposed-split weights, manual offsets (total 5505024 elems)
__device__ __align__(16) __nv_bfloat16 g_Wh[5505024];
__device__ __align__(16) __nv_bfloat16 g_Wlo[5505024];
__device__ int   g_deg[NN];
__device__ int   g_fill[NN];
__device__ int   g_rowptr[NN + 1];
__device__ int   g_col[EE];
__device__ float g_dinv[NN];

// ================= helpers (baseline PTX, sm_80+) =================
__device__ __forceinline__ uint32_t smem_u32(const void* p) {
    uint32_t a;
    asm("{ .reg .u64 t; cvta.to.shared.u64 t, %1; cvt.u32.u64 %0, t; }" : "=r"(a) : "l"(p));
    return a;
}
__device__ __forceinline__ void ldm_x4(uint32_t* r, uint32_t addr) {
    asm volatile("ldmatrix.sync.aligned.m8n8.x4.shared.b16 {%0,%1,%2,%3}, [%4];"
        : "=r"(r[0]), "=r"(r[1]), "=r"(r[2]), "=r"(r[3]) : "r"(addr));
}
__device__ __forceinline__ void mma16816(float* c, const uint32_t* a, const uint32_t* b) {
    asm volatile("mma.sync.aligned.m16n8k16.row.col.f32.bf16.bf16.f32 "
        "{%0,%1,%2,%3}, {%4,%5,%6,%7}, {%8,%9}, {%0,%1,%2,%3};"
        : "+f"(c[0]), "+f"(c[1]), "+f"(c[2]), "+f"(c[3])
        : "r"(a[0]), "r"(a[1]), "r"(a[2]), "r"(a[3]), "r"(b[0]), "r"(b[1]));
}
__device__ __forceinline__ uint32_t sw128(uint32_t off) {
    return off ^ ((off >> 3) & 0x70);
}
__device__ __forceinline__ uint32_t pack_bf2(float a, float b) {
    __nv_bfloat162 v = __halves2bfloat162(__float2bfloat16(a), __float2bfloat16(b));
    return *(uint32_t*)&v;
}
#define CP_ASYNC16(saddr, gptr) \
    asm volatile("cp.async.cg.shared.global [%0], [%1], 16;" :: "r"(saddr), "l"(gptr))
#define CP_COMMIT() asm volatile("cp.async.commit_group;")
#define CP_WAIT1()  asm volatile("cp.async.wait_group 1;")

// ================= CSR construction (edge_index int32) =================
__global__ void zero_counts_kernel() {
    int i = blockIdx.x * blockDim.x + threadIdx.x;
    if (i < NN) { g_deg[i] = 0; g_fill[i] = 0; }
}
__global__ void count_deg_kernel(const int* __restrict__ ei) {
    int e = blockIdx.x * blockDim.x + threadIdx.x;
    if (e < EE) {
        int dst = ei[EE + e];
        if ((unsigned)dst < NN) atomicAdd(&g_deg[dst], 1);
    }
}
__global__ void scan_deg_kernel() {
    __shared__ int sh[1024];
    int tid = threadIdx.x;
    int carry = 0;
    if (tid == 0) g_rowptr[0] = 0;
    for (int base = 0; base < NN; base += 1024) {
        int i = base + tid;
        int v = (i < NN) ? g_deg[i] : 0;
        sh[tid] = v;
        __syncthreads();
        for (int off = 1; off < 1024; off <<= 1) {
            int t = (tid >= off) ? sh[tid - off] : 0;
            __syncthreads();
            sh[tid] += t;
            __syncthreads();
        }
        if (i < NN) {
            g_rowptr[i + 1] = carry + sh[tid];
            g_dinv[i] = 1.0f / fmaxf((float)v, 1.0f);
        }
        int last = sh[1023];
        __syncthreads();
        carry += last;
    }
}
__global__ void fill_csr_kernel(const int* __restrict__ ei) {
    int e = blockIdx.x * blockDim.x + threadIdx.x;
    if (e < EE) {
        int src = ei[e];
        int dst = ei[EE + e];
        if ((unsigned)dst < NN && (unsigned)src < NN) {
            int p = atomicAdd(&g_fill[dst], 1);
            g_col[g_rowptr[dst] + p] = src;
        }
    }
}

// ================= weight prep: transpose + bf16 hi/lo split =================
__global__ void wprep_kernel(const float* __restrict__ W, int K, int N,
                             int off, int kofs, int K2) {
    int idx = blockIdx.x * blockDim.x + threadIdx.x;
    if (idx >= K * N) return;
    int n = idx / K, k = idx - n * K;
    float w = W[(size_t)k * N + n];
    __nv_bfloat16 hi = __float2bfloat16(w);
    float lo = w - __bfloat162float(hi);
    size_t d = (size_t)off + (size_t)n * K2 + kofs + k;
    g_Wh[d] = hi;
    g_Wlo[d] = __float2bfloat16(lo);
}

// split x into cols [768..1535] of buf0 rows (stride 1536)
__global__ void split_x_kernel(const float* __restrict__ x) {
    int idx = blockIdx.x * blockDim.x + threadIdx.x;
    if (idx >= NN * 768) return;
    int n = idx / 768, c = idx - n * 768;
    float w = x[idx];
    __nv_bfloat16 hi = __float2bfloat16(w);
    size_t d = (size_t)n * 1536 + 768 + c;
    g_Hh[d] = hi;
    g_Hl[d] = __float2bfloat16(w - __bfloat162float(hi));
}

// mean-aggregate x rows -> split -> cols [0..767] of buf0 rows (stride 1536)
__global__ __launch_bounds__(192) void aggx_kernel(const float* __restrict__ x) {
    const int node = blockIdx.x;
    const int tid = threadIdx.x;
    const int s = g_rowptr[node];
    const int e = g_rowptr[node + 1];
    float4 acc = make_float4(0.f, 0.f, 0.f, 0.f);
    __shared__ int nb[192];
    for (int base = s; base < e; base += 192) {
        int cnt = min(192, e - base);
        if (tid < cnt) nb[tid] = g_col[base + tid];
        __syncthreads();
        for (int j = 0; j < cnt; j++) {
            float4 v = ((const float4*)(x + (size_t)nb[j] * 768))[tid];
            acc.x += v.x; acc.y += v.y; acc.z += v.z; acc.w += v.w;
        }
        __syncthreads();
    }
    const float di = g_dinv[node];
    acc.x *= di; acc.y *= di; acc.z *= di; acc.w *= di;
    float hx = __bfloat162float(__float2bfloat16(acc.x));
    float hy = __bfloat162float(__float2bfloat16(acc.y));
    float hz = __bfloat162float(__float2bfloat16(acc.z));
    float hw = __bfloat162float(__float2bfloat16(acc.w));
    uint2 hp = make_uint2(pack_bf2(acc.x, acc.y), pack_bf2(acc.z, acc.w));
    uint2 lp = make_uint2(pack_bf2(acc.x - hx, acc.y - hy), pack_bf2(acc.z - hz, acc.w - hw));
    size_t d = (size_t)node * 1536 + tid * 4;
    *(uint2*)(g_Hh + d) = hp;
    *(uint2*)(g_Hl + d) = lp;
}

// ================= HMMA GEMM (3-stage pipeline) =================
// AB: 0 -> A from g_Hh/g_Hl, 1 -> A from g_H2h/g_H2l
// EPI: 0 -> fp32 out to (z ? g_B : g_A); gridDim.z = 2, weights woff_l/woff_r
// EPI: 1 -> fused bias+relu+split out to the OTHER buffer pair; gridDim.z = 1
#define STG 65536
#define NSTAGE 3
template <int AB, int EPI>
__global__ __launch_bounds__(256) void bgemm_kernel(
    int woff_l, int woff_r, const float* __restrict__ bias,
    int M, int Kd, int Nd)
{
    extern __shared__ __align__(1024) uint8_t dsm[];
    const __nv_bfloat16* Ah = AB ? g_H2h : g_Hh;
    const __nv_bfloat16* Al = AB ? g_H2l : g_Hl;
    const int tid = threadIdx.x;
    const int wid = tid >> 5;
    const int lane = tid & 31;
    const int m0 = blockIdx.y * 128;
    const int n0 = blockIdx.x * 128;
    const int woff = blockIdx.z ? woff_r : woff_l;
    const int warp_m = (wid & 1) * 64;
    const int warp_n = (wid >> 1) * 32;
    const uint32_t sb = smem_u32(dsm);

    const int lrow = tid >> 1;
    const int q = tid & 1;
    const int arow = min(m0 + lrow, M - 1);
    const __nv_bfloat16* gAh = Ah + (size_t)arow * Kd + q * 32;
    const __nv_bfloat16* gAl = Al + (size_t)arow * Kd + q * 32;
    const __nv_bfloat16* gBh = g_Wh + woff + (size_t)(n0 + lrow) * Kd + q * 32;
    const __nv_bfloat16* gBl = g_Wlo + woff + (size_t)(n0 + lrow) * Kd + q * 32;
    const uint32_t dbase = lrow * 128 + q * 64;

    float acc[4][4][4];
#pragma unroll
    for (int mi = 0; mi < 4; mi++)
#pragma unroll
        for (int ni = 0; ni < 4; ni++)
#pragma unroll
            for (int qq = 0; qq < 4; qq++) acc[mi][ni][qq] = 0.f;

    const int sub = lane >> 3;
    const int lr = lane & 7;
    const int nch = Kd >> 6;

    // prologue: issue chunks 0 and 1 as separate groups
    {
#pragma unroll
        for (int j = 0; j < 4; j++) {
            uint32_t o = sw128(dbase + j * 16);
            CP_ASYNC16(sb + o,         gAh + j * 8);
            CP_ASYNC16(sb + 16384 + o, gAl + j * 8);
            CP_ASYNC16(sb + 32768 + o, gBh + j * 8);
            CP_ASYNC16(sb + 49152 + o, gBl + j * 8);
        }
        CP_COMMIT();
        if (1 < nch) {
            uint32_t s1 = sb + STG;
#pragma unroll
            for (int j = 0; j < 4; j++) {
                uint32_t o = sw128(dbase + j * 16);
                CP_ASYNC16(s1 + o,         gAh + 64 + j * 8);
                CP_ASYNC16(s1 + 16384 + o, gAl + 64 + j * 8);
                CP_ASYNC16(s1 + 32768 + o, gBh + 64 + j * 8);
                CP_ASYNC16(s1 + 49152 + o, gBl + 64 + j * 8);
            }
        }
        CP_COMMIT();
    }

    int st = 0;                  // stage of current chunk
    int st2 = 2;                 // stage for chunk ch+2
    for (int ch = 0; ch < nch; ch++) {
        CP_WAIT1();              // chunk ch's group complete (<=1 newer pending)
        __syncthreads();         // data visible to all; stage st2's old readers done

        if (ch + 2 < nch) {
            const int k2 = (ch + 2) << 6;
            uint32_t s2 = sb + st2 * STG;
#pragma unroll
            for (int j = 0; j < 4; j++) {
                uint32_t o = sw128(dbase + j * 16);
                CP_ASYNC16(s2 + o,         gAh + k2 + j * 8);
                CP_ASYNC16(s2 + 16384 + o, gAl + k2 + j * 8);
                CP_ASYNC16(s2 + 32768 + o, gBh + k2 + j * 8);
                CP_ASYNC16(s2 + 49152 + o, gBl + k2 + j * 8);
            }
        }
        CP_COMMIT();

        const uint32_t sAh = sb + st * STG;
        const uint32_t sAl = sAh + 16384;
        const uint32_t sBh = sAh + 32768;
        const uint32_t sBl = sAh + 49152;

#pragma unroll
        for (int ks = 0; ks < 4; ks++) {
            uint32_t ah[4][4], al[4][4];
#pragma unroll
            for (int mi = 0; mi < 4; mi++) {
                int row = warp_m + mi * 16 + (sub & 1) * 8 + lr;
                uint32_t kb = ks * 32 + (sub >> 1) * 16;
                uint32_t o = sw128(row * 128 + kb);
                ldm_x4(ah[mi], sAh + o);
                ldm_x4(al[mi], sAl + o);
            }
            uint32_t bh[2][4], bl[2][4];
#pragma unroll
            for (int np = 0; np < 2; np++) {
                int row = warp_n + np * 16 + (sub >> 1) * 8 + lr;
                uint32_t kb = ks * 32 + (sub & 1) * 16;
                uint32_t o = sw128(row * 128 + kb);
                ldm_x4(bh[np], sBh + o);
                ldm_x4(bl[np], sBl + o);
            }
#pragma unroll
            for (int mi = 0; mi < 4; mi++)
#pragma unroll
                for (int ni = 0; ni < 4; ni++) {
                    const uint32_t* ph = &bh[ni >> 1][(ni & 1) * 2];
                    const uint32_t* pl = &bl[ni >> 1][(ni & 1) * 2];
                    mma16816(acc[mi][ni], ah[mi], ph);
                    mma16816(acc[mi][ni], ah[mi], pl);
                    mma16816(acc[mi][ni], al[mi], ph);
                }
        }
        st = (st == 2) ? 0 : st + 1;
        st2 = (st2 == 2) ? 0 : st2 + 1;
    }

    // ---- epilogue ----
    const int g = lane >> 2;
    const int t = lane & 3;
    if constexpr (EPI == 0) {
        float* C = blockIdx.z ? g_B : g_A;
#pragma unroll
        for (int mi = 0; mi < 4; mi++) {
            int r0 = m0 + warp_m + mi * 16 + g;
            int r1 = r0 + 8;
#pragma unroll
            for (int ni = 0; ni < 4; ni++) {
                int col = n0 + warp_n + ni * 8 + t * 2;
                if (r0 < M) *(float2*)(C + (size_t)r0 * Nd + col) = make_float2(acc[mi][ni][0], acc[mi][ni][1]);
                if (r1 < M) *(float2*)(C + (size_t)r1 * Nd + col) = make_float2(acc[mi][ni][2], acc[mi][ni][3]);
            }
        }
    } else {
        __nv_bfloat16* Oh = AB ? g_Hh : g_H2h;
        __nv_bfloat16* Ol = AB ? g_Hl : g_H2l;
#pragma unroll
        for (int mi = 0; mi < 4; mi++) {
            int r0 = m0 + warp_m + mi * 16 + g;
            int r1 = r0 + 8;
#pragma unroll
            for (int ni = 0; ni < 4; ni++) {
                int col = n0 + warp_n + ni * 8 + t * 2;
                float b0 = bias[col], b1v = bias[col + 1];
                float v0 = fmaxf(acc[mi][ni][0] + b0, 0.f);
                float v1 = fmaxf(acc[mi][ni][1] + b1v, 0.f);
                float v2 = fmaxf(acc[mi][ni][2] + b0, 0.f);
                float v3 = fmaxf(acc[mi][ni][3] + b1v, 0.f);
                float h0 = __bfloat162float(__float2bfloat16(v0));
                float h1 = __bfloat162float(__float2bfloat16(v1));
                float h2 = __bfloat162float(__float2bfloat16(v2));
                float h3 = __bfloat162float(__float2bfloat16(v3));
                if (r0 < M) {
                    *(uint32_t*)(Oh + (size_t)r0 * Nd + col) = pack_bf2(v0, v1);
                    *(uint32_t*)(Ol + (size_t)r0 * Nd + col) = pack_bf2(v0 - h0, v1 - h1);
                }
                if (r1 < M) {
                    *(uint32_t*)(Oh + (size_t)r1 * Nd + col) = pack_bf2(v2, v3);
                    *(uint32_t*)(Ol + (size_t)r1 * Nd + col) = pack_bf2(v2 - h2, v3 - h3);
                }
            }
        }
    }
}

// ================= small-N GEMM for the final 256->5 linear =================
__global__ void gemm_small_kernel(const float* __restrict__ Aext,
                                  const float* __restrict__ W,
                                  int zsel, int M, int Kd, int Nd)
{
    float* C = zsel ? g_B : g_A;
    int idx = blockIdx.x * blockDim.x + threadIdx.x;
    if (idx >= M * Nd) return;
    int row = idx / Nd, c = idx % Nd;
    const float* a = Aext + (size_t)row * Kd;
    float acc = 0.f;
    for (int k = 0; k < Kd; k++) acc += a[k] * W[k * Nd + c];
    C[idx] = acc;
}

// ================= combine (layers 2-4): r = relu(di*agg(g_A) + g_B + b) ===
template <int F, int OM>
__global__ void combine_kernel(const float* __restrict__ bias,
                               float* __restrict__ outExt)
{
    constexpr int NT = F / 4;
    const int node = blockIdx.x;
    const int tid = threadIdx.x;
    const int s = g_rowptr[node];
    const int e = g_rowptr[node + 1];

    float4 acc = make_float4(0.f, 0.f, 0.f, 0.f);
    __shared__ int nb[NT];
    for (int base = s; base < e; base += NT) {
        int cnt = min(NT, e - base);
        if (tid < cnt) nb[tid] = g_col[base + tid];
        __syncthreads();
        for (int j = 0; j < cnt; j++) {
            float4 v = ((const float4*)(g_A + (size_t)nb[j] * F))[tid];
            acc.x += v.x; acc.y += v.y; acc.z += v.z; acc.w += v.w;
        }
        __syncthreads();
    }

    const float di = g_dinv[node];
    float4 sv = ((const float4*)(g_B + (size_t)node * F))[tid];
    float4 bv = ((const float4*)bias)[tid];
    float rx = fmaxf(acc.x * di + sv.x + bv.x, 0.f);
    float ry = fmaxf(acc.y * di + sv.y + bv.y, 0.f);
    float rz = fmaxf(acc.z * di + sv.z + bv.z, 0.f);
    float rw = fmaxf(acc.w * di + sv.w + bv.w, 0.f);

    if constexpr (OM == 0) {
        ((float4*)(outExt + (size_t)node * F))[tid] = make_float4(rx, ry, rz, rw);
    } else {
        __nv_bfloat16* Oh = (OM == 1) ? g_Hh : g_H2h;
        __nv_bfloat16* Ol = (OM == 1) ? g_Hl : g_H2l;
        float hx = __bfloat162float(__float2bfloat16(rx));
        float hy = __bfloat162float(__float2bfloat16(ry));
        float hz = __bfloat162float(__float2bfloat16(rz));
        float hw = __bfloat162float(__float2bfloat16(rw));
        size_t d = (size_t)node * F + tid * 4;
        *(uint2*)(Oh + d) = make_uint2(pack_bf2(rx, ry), pack_bf2(rz, rw));
        *(uint2*)(Ol + d) = make_uint2(pack_bf2(rx - hx, ry - hy), pack_bf2(rz - hz, rw - hw));
    }
}

__global__ void combine5_kernel(const float* __restrict__ bias,
                                float* __restrict__ out)
{
    int node = blockIdx.x * 4 + (threadIdx.x >> 5);
    if (node >= NN) return;
    int lane = threadIdx.x & 31;
    if (lane >= 5) return;
    int s = g_rowptr[node], e = g_rowptr[node + 1];
    float acc = 0.f;
    for (int j = s; j < e; j++) acc += g_A[g_col[j] * 5 + lane];
    out[node * 5 + lane] = acc * g_dinv[node] + g_B[node * 5 + lane] + bias[lane];
}

// ================= launch =================
extern "C" void kernel_launch(void* const* d_in, const int* in_sizes, int n_in,
                              void* d_out, int out_size)
{
    const float* x  = (const float*)d_in[0];
    const int*   ei = (const int*)d_in[1];
    const float* Wl1 = (const float*)d_in[2];
    const float* Wr1 = (const float*)d_in[3];
    const float* b1  = (const float*)d_in[4];
    const float* Wl2 = (const float*)d_in[5];
    const float* Wr2 = (const float*)d_in[6];
    const float* b2  = (const float*)d_in[7];
    const float* Wl3 = (const float*)d_in[8];
    const float* Wr3 = (const float*)d_in[9];
    const float* b3  = (const float*)d_in[10];
    const float* Wl4 = (const float*)d_in[11];
    const float* Wr4 = (const float*)d_in[12];
    const float* b4  = (const float*)d_in[13];
    const float* Wl5 = (const float*)d_in[14];
    const float* Wr5 = (const float*)d_in[15];
    const float* b5  = (const float*)d_in[16];

    float* out = (float*)d_out;
    float* out_h   = out;                      // [NN, 256]
    float* out_cls = out + (size_t)NN * 256;   // [NN, 5]

    const int SMEM_SZ = NSTAGE * STG;   // 192 KB
    cudaFuncSetAttribute(bgemm_kernel<0, 1>, cudaFuncAttributeMaxDynamicSharedMemorySize, SMEM_SZ);
    cudaFuncSetAttribute(bgemm_kernel<1, 0>, cudaFuncAttributeMaxDynamicSharedMemorySize, SMEM_SZ);
    cudaFuncSetAttribute(bgemm_kernel<0, 0>, cudaFuncAttributeMaxDynamicSharedMemorySize, SMEM_SZ);

    // ---- CSR build ----
    zero_counts_kernel<<<(NN + 255) / 256, 256>>>();
    count_deg_kernel<<<(EE + 255) / 256, 256>>>(ei);
    scan_deg_kernel<<<1, 1024>>>();
    fill_csr_kernel<<<(EE + 255) / 256, 256>>>(ei);

    // ---- weight prep ----
    const int OFF1 = 0;
    const int OFF2L = 2359296, OFF2R = 3538944;
    const int OFF3L = 4718592, OFF3R = 5013504;
    const int OFF4L = 5308416, OFF4R = 5406720;
    wprep_kernel<<<(768 * 1536 + 255) / 256, 256>>>(Wl1, 768, 1536, OFF1, 0, 1536);
    wprep_kernel<<<(768 * 1536 + 255) / 256, 256>>>(Wr1, 768, 1536, OFF1, 768, 1536);
    wprep_kernel<<<(1536 * 768 + 255) / 256, 256>>>(Wl2, 1536, 768, OFF2L, 0, 1536);
    wprep_kernel<<<(1536 * 768 + 255) / 256, 256>>>(Wr2, 1536, 768, OFF2R, 0, 1536);
    wprep_kernel<<<(768 * 384 + 255) / 256, 256>>>(Wl3, 768, 384, OFF3L, 0, 768);
    wprep_kernel<<<(768 * 384 + 255) / 256, 256>>>(Wr3, 768, 384, OFF3R, 0, 768);
    wprep_kernel<<<(384 * 256 + 255) / 256, 256>>>(Wl4, 384, 256, OFF4L, 0, 384);
    wprep_kernel<<<(384 * 256 + 255) / 256, 256>>>(Wr4, 384, 256, OFF4R, 0, 384);

    // ---- input prep ----
    split_x_kernel<<<(NN * 768 + 255) / 256, 256>>>(x);
    aggx_kernel<<<NN, 192>>>(x);

    const int M = NN;
    const int gy = (M + 127) / 128;   // 157

    // ---- Layer 1: fused [agg|x] @ [[Wl],[Wr]] (K=1536) + bias+relu+split ----
    bgemm_kernel<0, 1><<<dim3(12, gy, 1), 256, SMEM_SZ>>>(OFF1, OFF1, b1, M, 1536, 1536);  // -> buf1

    // ---- Layer 2: 1536 -> 768 ----
    bgemm_kernel<1, 0><<<dim3(6, gy, 2), 256, SMEM_SZ>>>(OFF2L, OFF2R, nullptr, M, 1536, 768);
    combine_kernel<768, 1><<<NN, 192>>>(b2, nullptr);     // -> buf0

    // ---- Layer 3: 768 -> 384 ----
    bgemm_kernel<0, 0><<<dim3(3, gy, 2), 256, SMEM_SZ>>>(OFF3L, OFF3R, nullptr, M, 768, 384);
    combine_kernel<384, 2><<<NN, 96>>>(b3, nullptr);      // -> buf1

    // ---- Layer 4: 384 -> 256 (h output fp32) ----
    bgemm_kernel<1, 0><<<dim3(2, gy, 2), 256, SMEM_SZ>>>(OFF4L, OFF4R, nullptr, M, 384, 256);
    combine_kernel<256, 0><<<NN, 64>>>(b4, out_h);        // -> d_out h region

    // ---- Layer 5: 256 -> 5 (no relu) ----
    gemm_small_kernel<<<(NN * 5 + 255) / 256, 256>>>(out_h, Wl5, 0, M, 256, 5);
    gemm_small_kernel<<<(NN * 5 + 255) / 256, 256>>>(out_h, Wr5, 1, M, 256, 5);
    combine5_kernel<<<(NN + 3) / 4, 128>>>(b5, out_cls);
}